// round 11
// baseline (speedup 1.0000x reference)
#include <cuda_runtime.h>
#include <cuda_fp16.h>
#include <math.h>

#define N_NODES 100000
#define N_EDGES 3200000
#define D 64
#define NEG_SLOPE 0.01f
#define NTILES ((N_NODES + 255) / 256)   // 391

#define NPB 128          // nodes per fused block
#define TPB 512          // 4 threads/node (gather); 16 warps (mma)
#define AB_STRIDE_H 136  // halves per ab row  (272B: 4-word bank rotation)
#define W_STRIDE_H 72    // halves per weight row (144B: same rotation)
#define SMEM_AB_BYTES (NPB * AB_STRIDE_H * 2)      // 34816
#define SMEM_W_BYTES  (128 * W_STRIDE_H * 2)       // 18432
#define SMEM_BYTES    (SMEM_AB_BYTES + SMEM_W_BYTES)  // 53248

// ---------------- device scratch (no allocations allowed) ----------------
__device__ __half g_xh [N_NODES * D];   // fp16 x
__device__ __half g_hAh[N_NODES * D];   // fp16 h1
__device__ __half g_hBh[N_NODES * D];   // fp16 h2
__device__ float  g_rsq[N_NODES];
__device__ int    g_deg[N_NODES];
__device__ int    g_off[N_NODES + 1];
__device__ int    g_cur[N_NODES];
__device__ int2   g_edge[N_EDGES];      // {src, bitcast(w)} grouped by dst
__device__ int                g_ticket;
__device__ unsigned long long g_state[NTILES];

// ---------------- precompute kernels (unchanged, known-good) -------------
__global__ void k_count(const int* __restrict__ dst) {
    int e = blockIdx.x * blockDim.x + threadIdx.x;
    if (e < N_EDGES) atomicAdd(&g_deg[dst[e]], 1);
}

__global__ void __launch_bounds__(256) k_scan() {
    __shared__ int sh[256];
    __shared__ int s_tile, s_excl;
    int tid = threadIdx.x;
    if (tid == 0) s_tile = atomicAdd(&g_ticket, 1);
    __syncthreads();
    int tile = s_tile;
    int i = tile * 256 + tid;
    int deg = (i < N_NODES) ? g_deg[i] : 0;
    int val = deg;
    sh[tid] = val;
    __syncthreads();
    for (int ofs = 1; ofs < 256; ofs <<= 1) {
        int t = (tid >= ofs) ? sh[tid - ofs] : 0;
        __syncthreads();
        val += t;
        sh[tid] = val;
        __syncthreads();
    }
    int total = sh[255];

    volatile unsigned long long* st = g_state;
    if (tile == 0) {
        if (tid == 0) {
            st[0] = ((unsigned long long)total << 2) | 2ULL;
            s_excl = 0;
        }
    } else {
        if (tid == 0)
            st[tile] = ((unsigned long long)total << 2) | 1ULL;
        if (tid < 32) {
            int excl = 0;
            int t = tile - 1;
            while (true) {
                int idx = t - tid;
                unsigned long long s;
                if (idx >= 0) {
                    do { s = st[idx]; } while ((s & 3ULL) == 0ULL);
                } else {
                    s = 2ULL;
                }
                unsigned pm = __ballot_sync(0xffffffffu, (s & 3ULL) == 2ULL);
                int value = (int)(s >> 2);
                if (pm) {
                    int pl = __ffs(pm) - 1;
                    int contrib = (tid <= pl) ? value : 0;
                    excl += __reduce_add_sync(0xffffffffu, contrib);
                    break;
                } else {
                    excl += __reduce_add_sync(0xffffffffu, value);
                    t -= 32;
                }
            }
            if (tid == 0) {
                st[tile] = ((unsigned long long)(excl + total) << 2) | 2ULL;
                s_excl = excl;
            }
        }
    }
    __syncthreads();
    int base = s_excl;
    if (i < N_NODES) {
        int o = base + val - deg;
        g_off[i] = o;
        g_cur[i] = o;
        g_rsq[i] = rsqrtf((float)(deg > 0 ? deg : 1));
    }
    if (tile == 0 && tid == 0) g_off[N_NODES] = N_EDGES;
}

__global__ void k_fill_tohalf(const int* __restrict__ src,
                              const int* __restrict__ dst,
                              const float* __restrict__ x) {
    int i = blockIdx.x * blockDim.x + threadIdx.x;
    if (i < N_NODES * D / 4) {
        float4 v = ((const float4*)x)[i];
        half2 a = __floats2half2_rn(v.x, v.y);
        half2 b = __floats2half2_rn(v.z, v.w);
        uint2 o;
        o.x = *(unsigned int*)&a;
        o.y = *(unsigned int*)&b;
        ((uint2*)g_xh)[i] = o;
    }
    if (i < N_EDGES) {
        int d = dst[i];
        int s = src[i];
        float w = g_rsq[s] * g_rsq[d];
        int pos = atomicAdd(&g_cur[d], 1);
        g_edge[pos] = make_int2(s, __float_as_int(w));
    }
}

// ---------------- mma helpers ----------------
__device__ __forceinline__ unsigned smem_u32(const void* p) {
    return (unsigned)__cvta_generic_to_shared(p);
}
__device__ __forceinline__ void ldmatrix_x4(unsigned* a, unsigned addr) {
    asm volatile("ldmatrix.sync.aligned.m8n8.x4.shared.b16 {%0,%1,%2,%3}, [%4];"
                 : "=r"(a[0]), "=r"(a[1]), "=r"(a[2]), "=r"(a[3]) : "r"(addr));
}
__device__ __forceinline__ void ldmatrix_x2_trans(unsigned* b, unsigned addr) {
    asm volatile("ldmatrix.sync.aligned.m8n8.x2.trans.shared.b16 {%0,%1}, [%2];"
                 : "=r"(b[0]), "=r"(b[1]) : "r"(addr));
}
__device__ __forceinline__ void mma16816(float* d, const unsigned* a,
                                         const unsigned* b) {
    asm volatile(
        "mma.sync.aligned.m16n8k16.row.col.f32.f16.f16.f32 "
        "{%0,%1,%2,%3}, {%4,%5,%6,%7}, {%8,%9}, {%0,%1,%2,%3};"
        : "+f"(d[0]), "+f"(d[1]), "+f"(d[2]), "+f"(d[3])
        : "r"(a[0]), "r"(a[1]), "r"(a[2]), "r"(a[3]), "r"(b[0]), "r"(b[1]));
}

// ---------------- fused layer: gather (SIMT) + matvec (HMMA) -------------
__device__ __forceinline__ void acc8h(float* acc, uint4 v, float w) {
    float2 f0 = __half22float2(*(half2*)&v.x);
    float2 f1 = __half22float2(*(half2*)&v.y);
    float2 f2 = __half22float2(*(half2*)&v.z);
    float2 f3 = __half22float2(*(half2*)&v.w);
    acc[0] += w * f0.x; acc[1] += w * f0.y;
    acc[2] += w * f1.x; acc[3] += w * f1.y;
    acc[4] += w * f2.x; acc[5] += w * f2.y;
    acc[6] += w * f3.x; acc[7] += w * f3.y;
}
__device__ __forceinline__ void cvt8(float* f, uint4 v) {
    float2 f0 = __half22float2(*(half2*)&v.x);
    float2 f1 = __half22float2(*(half2*)&v.y);
    float2 f2 = __half22float2(*(half2*)&v.z);
    float2 f3 = __half22float2(*(half2*)&v.w);
    f[0] = f0.x; f[1] = f0.y; f[2] = f1.x; f[3] = f1.y;
    f[4] = f2.x; f[5] = f2.y; f[6] = f3.x; f[7] = f3.y;
}

__global__ void __launch_bounds__(TPB, 2) k_fused(
    const __half* __restrict__ hh,
    const float* __restrict__ W1,
    const float* __restrict__ W2,
    float* __restrict__ out,          // [N,192] at colOff
    __half* __restrict__ houtH,       // may be null
    int do_relu, int colOff)
{
    extern __shared__ __align__(16) __half smem_h[];
    __half* sab = smem_h;                           // [NPB][AB_STRIDE_H]
    __half* sW  = smem_h + NPB * AB_STRIDE_H;       // [128][W_STRIDE_H]

    int tid = threadIdx.x;

    // ---- stage fp16 weights: rows 0..63 = W1[k][n], 64..127 = W2[k][n] ----
    for (int i = tid; i < 8192; i += TPB) {
        int k = i >> 6, n = i & 63;
        float v = (k < 64) ? W1[i] : W2[i - 4096];
        sW[k * W_STRIDE_H + n] = __float2half(v);
    }

    // ---- gather: 4 threads/node, node-local cols 8c..8c+7 and +32 ----
    int nl = tid >> 2;                 // 0..127
    int c  = tid & 3;
    int node = blockIdx.x * NPB + nl;
    if (node < N_NODES) {
        float acc[16];
#pragma unroll
        for (int j = 0; j < 16; j++) acc[j] = 0.f;
        int e = g_off[node];
        int end = g_off[node + 1];
        const uint4* h4 = (const uint4*)hh;
        int2 E0 = make_int2(0, 0), E1 = make_int2(0, 0);
        if (e < end) E0 = g_edge[e];
        if (e + 1 < end) E1 = g_edge[e + 1];
        while (e < end) {
            int en = e + 2;
            int2 P0 = make_int2(0, 0), P1 = make_int2(0, 0);
            if (en < end) P0 = g_edge[en];
            if (en + 1 < end) P1 = g_edge[en + 1];
            size_t r0 = (size_t)E0.x * 8;
            uint4 v0a = h4[r0 + c];
            uint4 v0b = h4[r0 + c + 4];
            float w0 = __int_as_float(E0.y);
            acc8h(acc, v0a, w0);
            acc8h(acc + 8, v0b, w0);
            if (e + 1 < end) {
                size_t r1 = (size_t)E1.x * 8;
                uint4 v1a = h4[r1 + c];
                uint4 v1b = h4[r1 + c + 4];
                float w1v = __int_as_float(E1.y);
                acc8h(acc, v1a, w1v);
                acc8h(acc + 8, v1b, w1v);
            }
            E0 = P0; E1 = P1; e = en;
        }

        // a = x+s -> k cols [8c..8c+7] and [8c+32..]; b = x*s -> +64
        uint4 xv0 = ((const uint4*)(hh + (size_t)node * D))[c];
        uint4 xv1 = ((const uint4*)(hh + (size_t)node * D))[c + 4];
        float xf0[8], xf1[8];
        cvt8(xf0, xv0);
        cvt8(xf1, xv1);
        __half* row = sab + nl * AB_STRIDE_H;
        half2 pa[4], pb[4];
#pragma unroll
        for (int j = 0; j < 4; j++) {
            pa[j] = __floats2half2_rn(xf0[2*j] + acc[2*j], xf0[2*j+1] + acc[2*j+1]);
            pb[j] = __floats2half2_rn(xf0[2*j] * acc[2*j], xf0[2*j+1] * acc[2*j+1]);
        }
        *(uint4*)(row + 8 * c)      = *(uint4*)pa;   // a, k = 8c..8c+7
        *(uint4*)(row + 64 + 8 * c) = *(uint4*)pb;   // b, k = 64+8c..
#pragma unroll
        for (int j = 0; j < 4; j++) {
            pa[j] = __floats2half2_rn(xf1[2*j] + acc[8+2*j], xf1[2*j+1] + acc[8+2*j+1]);
            pb[j] = __floats2half2_rn(xf1[2*j] * acc[8+2*j], xf1[2*j+1] * acc[8+2*j+1]);
        }
        *(uint4*)(row + 32 + 8 * c) = *(uint4*)pa;   // a, k = 32+8c..
        *(uint4*)(row + 96 + 8 * c) = *(uint4*)pb;   // b, k = 96+8c..
    }
    __syncthreads();

    // ---- HMMA matvec: warp w -> rtile = w>>1, ctiles (w&1)*4 .. +3 ----
    int w = tid >> 5;
    int lane = tid & 31;
    int rtile = w >> 1;
    int cbase = (w & 1) * 4;

    float d[4][4];
#pragma unroll
    for (int i = 0; i < 4; i++)
#pragma unroll
        for (int j = 0; j < 4; j++) d[i][j] = 0.f;

    // A-fragment address: row = 16*rtile + (lane&15), col half-offset (lane>>4)*8
    unsigned a_addr = smem_u32(sab + (16 * rtile + (lane & 15)) * AB_STRIDE_H
                               + ((lane >> 4) << 3));
#pragma unroll
    for (int ks = 0; ks < 8; ks++) {
        unsigned afr[4];
        ldmatrix_x4(afr, a_addr + ks * 32);   // +16 halves per kstep = 32B
#pragma unroll
        for (int ci = 0; ci < 4; ci++) {
            int cb = (cbase + ci) << 3;       // absolute col base
            unsigned b_addr = smem_u32(sW + (ks * 16 + (lane & 15)) * W_STRIDE_H + cb);
            unsigned bfr[2];
            ldmatrix_x2_trans(bfr, b_addr);
            mma16816(d[ci], afr, bfr);
        }
    }

    // ---- epilogue ----
    int r0 = lane >> 2;
    int cc = (lane & 3) << 1;
    int node0 = blockIdx.x * NPB + 16 * rtile + r0;
    int node1 = node0 + 8;
#pragma unroll
    for (int ci = 0; ci < 4; ci++) {
        int col = ((cbase + ci) << 3) + cc;
        float v0 = d[ci][0], v1 = d[ci][1], v2 = d[ci][2], v3 = d[ci][3];
        if (do_relu) {
            v0 = v0 > 0.f ? v0 : NEG_SLOPE * v0;
            v1 = v1 > 0.f ? v1 : NEG_SLOPE * v1;
            v2 = v2 > 0.f ? v2 : NEG_SLOPE * v2;
            v3 = v3 > 0.f ? v3 : NEG_SLOPE * v3;
        }
        if (node0 < N_NODES) {
            *(float2*)(out + (size_t)node0 * 192 + colOff + col) =
                make_float2(v0, v1);
            if (houtH) {
                half2 h = __floats2half2_rn(v0, v1);
                *(unsigned*)(houtH + (size_t)node0 * D + col) = *(unsigned*)&h;
            }
        }
        if (node1 < N_NODES) {
            *(float2*)(out + (size_t)node1 * 192 + colOff + col) =
                make_float2(v2, v3);
            if (houtH) {
                half2 h = __floats2half2_rn(v2, v3);
                *(unsigned*)(houtH + (size_t)node1 * D + col) = *(unsigned*)&h;
            }
        }
    }
}

// ---------------- launch ----------------
extern "C" void kernel_launch(void* const* d_in, const int* in_sizes, int n_in,
                              void* d_out, int out_size) {
    const float* x   = (const float*)d_in[0];
    const float* W1a = (const float*)d_in[1];
    const float* W2a = (const float*)d_in[2];
    const float* W1b = (const float*)d_in[3];
    const float* W2b = (const float*)d_in[4];
    const int*   src = (const int*)d_in[5];
    const int*   dst = (const int*)d_in[6];
    float* out = (float*)d_out;

    __half* xh;  cudaGetSymbolAddress((void**)&xh,  g_xh);
    __half* hAh; cudaGetSymbolAddress((void**)&hAh, g_hAh);
    __half* hBh; cudaGetSymbolAddress((void**)&hBh, g_hBh);
    void* degP;  cudaGetSymbolAddress(&degP, g_deg);
    void* tkP;   cudaGetSymbolAddress(&tkP, g_ticket);
    void* stP;   cudaGetSymbolAddress(&stP, g_state);

    cudaFuncSetAttribute(k_fused, cudaFuncAttributeMaxDynamicSharedMemorySize,
                         SMEM_BYTES);

    const int TB = 256;
    int gE = (N_EDGES + TB - 1) / TB;
    int gF = (N_NODES + NPB - 1) / NPB;   // 782

    cudaMemsetAsync(degP, 0, N_NODES * sizeof(int));
    cudaMemsetAsync(tkP, 0, sizeof(int));
    cudaMemsetAsync(stP, 0, NTILES * sizeof(unsigned long long));

    k_count<<<gE, TB>>>(dst);
    k_scan<<<NTILES, 256>>>();
    k_fill_tohalf<<<gE, TB>>>(src, dst, x);

    k_fused<<<gF, TPB, SMEM_BYTES>>>(xh, W1a, W2a, out, hAh, 1, 0);
    k_fused<<<gF, TPB, SMEM_BYTES>>>(hAh, W1b, W2b, out, hBh, 1, 64);
    k_fused<<<gF, TPB, SMEM_BYTES>>>(hBh, W1b, W2b, out, (__half*)0, 0, 128);
}

// round 12
// speedup vs baseline: 1.0808x; 1.0808x over previous
#include <cuda_runtime.h>
#include <cuda_fp16.h>
#include <math.h>

#define N_NODES 100000
#define N_EDGES 3200000
#define D 64
#define NEG_SLOPE 0.01f
#define NTILES ((N_NODES + 255) / 256)   // 391

#define NPB 64           // nodes per fused block
#define TPB 512          // 8 threads/node (gather); 16 warps (mma)
#define AB_STRIDE_H 136  // halves per ab row (272B: conflict-free rotation)
#define W_STRIDE_H 72    // halves per weight row (144B: same rotation)
#define SMEM_AB_BYTES (NPB * AB_STRIDE_H * 2)        // 17408
#define SMEM_W_BYTES  (128 * W_STRIDE_H * 2)         // 18432
#define SMEM_BYTES    (SMEM_AB_BYTES + SMEM_W_BYTES) // 35840

// ---------------- device scratch (no allocations allowed) ----------------
__device__ __half g_xh [N_NODES * D];   // fp16 x
__device__ __half g_hAh[N_NODES * D];   // fp16 h1
__device__ __half g_hBh[N_NODES * D];   // fp16 h2
__device__ __half g_w16[2][8192];       // fp16 weights: [layerSel][k*64+n], k<64=W1,k>=64=W2
__device__ float  g_rsq[N_NODES];
__device__ int    g_deg[N_NODES];
__device__ int    g_off[N_NODES + 1];
__device__ int    g_cur[N_NODES];
__device__ int2   g_edge[N_EDGES];      // {src, bitcast(w)} grouped by dst
__device__ int                g_ticket;
__device__ unsigned long long g_state[NTILES];

// ---------------- precompute kernels ----------------
__global__ void k_count(const int* __restrict__ dst) {
    int e = blockIdx.x * blockDim.x + threadIdx.x;
    if (e < N_EDGES) atomicAdd(&g_deg[dst[e]], 1);
}

__global__ void __launch_bounds__(256) k_scan() {
    __shared__ int sh[256];
    __shared__ int s_tile, s_excl;
    int tid = threadIdx.x;
    if (tid == 0) s_tile = atomicAdd(&g_ticket, 1);
    __syncthreads();
    int tile = s_tile;
    int i = tile * 256 + tid;
    int deg = (i < N_NODES) ? g_deg[i] : 0;
    int val = deg;
    sh[tid] = val;
    __syncthreads();
    for (int ofs = 1; ofs < 256; ofs <<= 1) {
        int t = (tid >= ofs) ? sh[tid - ofs] : 0;
        __syncthreads();
        val += t;
        sh[tid] = val;
        __syncthreads();
    }
    int total = sh[255];

    volatile unsigned long long* st = g_state;
    if (tile == 0) {
        if (tid == 0) {
            st[0] = ((unsigned long long)total << 2) | 2ULL;
            s_excl = 0;
        }
    } else {
        if (tid == 0)
            st[tile] = ((unsigned long long)total << 2) | 1ULL;
        if (tid < 32) {
            int excl = 0;
            int t = tile - 1;
            while (true) {
                int idx = t - tid;
                unsigned long long s;
                if (idx >= 0) {
                    do { s = st[idx]; } while ((s & 3ULL) == 0ULL);
                } else {
                    s = 2ULL;
                }
                unsigned pm = __ballot_sync(0xffffffffu, (s & 3ULL) == 2ULL);
                int value = (int)(s >> 2);
                if (pm) {
                    int pl = __ffs(pm) - 1;
                    int contrib = (tid <= pl) ? value : 0;
                    excl += __reduce_add_sync(0xffffffffu, contrib);
                    break;
                } else {
                    excl += __reduce_add_sync(0xffffffffu, value);
                    t -= 32;
                }
            }
            if (tid == 0) {
                st[tile] = ((unsigned long long)(excl + total) << 2) | 2ULL;
                s_excl = excl;
            }
        }
    }
    __syncthreads();
    int base = s_excl;
    if (i < N_NODES) {
        int o = base + val - deg;
        g_off[i] = o;
        g_cur[i] = o;
        g_rsq[i] = rsqrtf((float)(deg > 0 ? deg : 1));
    }
    if (tile == 0 && tid == 0) g_off[N_NODES] = N_EDGES;
}

// CSR fill + fp16 conversion of x + fp16 conversion of all 4 weight mats
__global__ void k_fill_tohalf(const int* __restrict__ src,
                              const int* __restrict__ dst,
                              const float* __restrict__ x,
                              const float* __restrict__ W1a,
                              const float* __restrict__ W2a,
                              const float* __restrict__ W1b,
                              const float* __restrict__ W2b) {
    int i = blockIdx.x * blockDim.x + threadIdx.x;
    if (i < N_NODES * D / 4) {
        float4 v = ((const float4*)x)[i];
        half2 a = __floats2half2_rn(v.x, v.y);
        half2 b = __floats2half2_rn(v.z, v.w);
        uint2 o;
        o.x = *(unsigned int*)&a;
        o.y = *(unsigned int*)&b;
        ((uint2*)g_xh)[i] = o;
    }
    if (i < 4096) {
        g_w16[0][i]        = __float2half(W1a[i]);
        g_w16[0][4096 + i] = __float2half(W2a[i]);
        g_w16[1][i]        = __float2half(W1b[i]);
        g_w16[1][4096 + i] = __float2half(W2b[i]);
    }
    if (i < N_EDGES) {
        int d = dst[i];
        int s = src[i];
        float w = g_rsq[s] * g_rsq[d];
        int pos = atomicAdd(&g_cur[d], 1);
        g_edge[pos] = make_int2(s, __float_as_int(w));
    }
}

// ---------------- mma helpers ----------------
__device__ __forceinline__ unsigned smem_u32(const void* p) {
    return (unsigned)__cvta_generic_to_shared(p);
}
__device__ __forceinline__ void ldmatrix_x4(unsigned* a, unsigned addr) {
    asm volatile("ldmatrix.sync.aligned.m8n8.x4.shared.b16 {%0,%1,%2,%3}, [%4];"
                 : "=r"(a[0]), "=r"(a[1]), "=r"(a[2]), "=r"(a[3]) : "r"(addr));
}
__device__ __forceinline__ void ldmatrix_x2_trans(unsigned* b, unsigned addr) {
    asm volatile("ldmatrix.sync.aligned.m8n8.x2.trans.shared.b16 {%0,%1}, [%2];"
                 : "=r"(b[0]), "=r"(b[1]) : "r"(addr));
}
__device__ __forceinline__ void mma16816(float* d, const unsigned* a,
                                         const unsigned* b) {
    asm volatile(
        "mma.sync.aligned.m16n8k16.row.col.f32.f16.f16.f32 "
        "{%0,%1,%2,%3}, {%4,%5,%6,%7}, {%8,%9}, {%0,%1,%2,%3};"
        : "+f"(d[0]), "+f"(d[1]), "+f"(d[2]), "+f"(d[3])
        : "r"(a[0]), "r"(a[1]), "r"(a[2]), "r"(a[3]), "r"(b[0]), "r"(b[1]));
}

// ---------------- fused layer ----------------
__device__ __forceinline__ void acc8h(float* acc, uint4 v, float w) {
    float2 f0 = __half22float2(*(half2*)&v.x);
    float2 f1 = __half22float2(*(half2*)&v.y);
    float2 f2 = __half22float2(*(half2*)&v.z);
    float2 f3 = __half22float2(*(half2*)&v.w);
    acc[0] += w * f0.x; acc[1] += w * f0.y;
    acc[2] += w * f1.x; acc[3] += w * f1.y;
    acc[4] += w * f2.x; acc[5] += w * f2.y;
    acc[6] += w * f3.x; acc[7] += w * f3.y;
}
__device__ __forceinline__ void cvt8(float* f, uint4 v) {
    float2 f0 = __half22float2(*(half2*)&v.x);
    float2 f1 = __half22float2(*(half2*)&v.y);
    float2 f2 = __half22float2(*(half2*)&v.z);
    float2 f3 = __half22float2(*(half2*)&v.w);
    f[0] = f0.x; f[1] = f0.y; f[2] = f1.x; f[3] = f1.y;
    f[4] = f2.x; f[5] = f2.y; f[6] = f3.x; f[7] = f3.y;
}

// block = 64 nodes. Gather: 8 threads/node (lane c owns cols 8c..8c+7).
// Matvec: 16 warps, warp w -> rtile = w>>2 (16 rows), ctiles {2(w&3), 2(w&3)+1}.
__global__ void __launch_bounds__(TPB, 3) k_fused(
    const __half* __restrict__ hh,
    const __half* __restrict__ Wh,    // [128][64] fp16: k<64 = W1, k>=64 = W2
    float* __restrict__ out,          // [N,192] at colOff
    __half* __restrict__ houtH,       // may be null
    int do_relu, int colOff)
{
    extern __shared__ __align__(16) __half smem_h[];
    __half* sab = smem_h;                           // [NPB][AB_STRIDE_H]
    __half* sW  = smem_h + NPB * AB_STRIDE_H;       // [128][W_STRIDE_H]

    int tid = threadIdx.x;

    // ---- stage fp16 weights (pure copy, 2 uint4 per thread) ----
    for (int i = tid; i < 1024; i += TPB) {
        int k = i >> 3, j = i & 7;
        *(uint4*)(sW + k * W_STRIDE_H + j * 8) =
            *(const uint4*)(Wh + k * 64 + j * 8);
    }

    // ---- gather: 8 threads/node ----
    int nl = tid >> 3;                 // 0..63
    int c  = tid & 7;                  // chunk 0..7
    int node = blockIdx.x * NPB + nl;
    if (node < N_NODES) {
        float acc[8];
#pragma unroll
        for (int j = 0; j < 8; j++) acc[j] = 0.f;
        int e = g_off[node];
        int end = g_off[node + 1];
        const uint4* h4 = (const uint4*)hh;
        int2 E0 = make_int2(0, 0), E1 = make_int2(0, 0);
        if (e < end) E0 = g_edge[e];
        if (e + 1 < end) E1 = g_edge[e + 1];
        while (e < end) {
            int en = e + 2;
            int2 P0 = make_int2(0, 0), P1 = make_int2(0, 0);
            if (en < end) P0 = g_edge[en];
            if (en + 1 < end) P1 = g_edge[en + 1];
            uint4 v0 = h4[(size_t)E0.x * 8 + c];
            acc8h(acc, v0, __int_as_float(E0.y));
            if (e + 1 < end) {
                uint4 v1 = h4[(size_t)E1.x * 8 + c];
                acc8h(acc, v1, __int_as_float(E1.y));
            }
            E0 = P0; E1 = P1; e = en;
        }

        // a = x+s -> k cols 8c..8c+7 ; b = x*s -> k cols 64+8c..
        uint4 xv = ((const uint4*)(hh + (size_t)node * D))[c];
        float xf[8];
        cvt8(xf, xv);
        __half* row = sab + nl * AB_STRIDE_H;
        half2 pa[4], pb[4];
#pragma unroll
        for (int j = 0; j < 4; j++) {
            pa[j] = __floats2half2_rn(xf[2*j] + acc[2*j], xf[2*j+1] + acc[2*j+1]);
            pb[j] = __floats2half2_rn(xf[2*j] * acc[2*j], xf[2*j+1] * acc[2*j+1]);
        }
        *(uint4*)(row + 8 * c)      = *(uint4*)pa;
        *(uint4*)(row + 64 + 8 * c) = *(uint4*)pb;
    }
    __syncthreads();

    // ---- HMMA matvec ----
    int w = tid >> 5;
    int lane = tid & 31;
    int rtile = w >> 2;                // 0..3
    int cbase = (w & 3) * 2;           // ctiles cbase, cbase+1

    float d[2][4];
#pragma unroll
    for (int i = 0; i < 2; i++)
#pragma unroll
        for (int j = 0; j < 4; j++) d[i][j] = 0.f;

    unsigned a_addr = smem_u32(sab + (16 * rtile + (lane & 15)) * AB_STRIDE_H
                               + ((lane >> 4) << 3));
#pragma unroll
    for (int ks = 0; ks < 8; ks++) {
        unsigned afr[4];
        ldmatrix_x4(afr, a_addr + ks * 32);   // +16 halves = 32B per kstep
#pragma unroll
        for (int ci = 0; ci < 2; ci++) {
            int cb = (cbase + ci) << 3;
            unsigned b_addr = smem_u32(sW + (ks * 16 + (lane & 15)) * W_STRIDE_H + cb);
            unsigned bfr[2];
            ldmatrix_x2_trans(bfr, b_addr);
            mma16816(d[ci], afr, bfr);
        }
    }

    // ---- epilogue ----
    int r0 = lane >> 2;
    int cc = (lane & 3) << 1;
    int node0 = blockIdx.x * NPB + 16 * rtile + r0;
    int node1 = node0 + 8;
#pragma unroll
    for (int ci = 0; ci < 2; ci++) {
        int col = ((cbase + ci) << 3) + cc;
        float v0 = d[ci][0], v1 = d[ci][1], v2 = d[ci][2], v3 = d[ci][3];
        if (do_relu) {
            v0 = v0 > 0.f ? v0 : NEG_SLOPE * v0;
            v1 = v1 > 0.f ? v1 : NEG_SLOPE * v1;
            v2 = v2 > 0.f ? v2 : NEG_SLOPE * v2;
            v3 = v3 > 0.f ? v3 : NEG_SLOPE * v3;
        }
        if (node0 < N_NODES) {
            *(float2*)(out + (size_t)node0 * 192 + colOff + col) =
                make_float2(v0, v1);
            if (houtH) {
                half2 h = __floats2half2_rn(v0, v1);
                *(unsigned*)(houtH + (size_t)node0 * D + col) = *(unsigned*)&h;
            }
        }
        if (node1 < N_NODES) {
            *(float2*)(out + (size_t)node1 * 192 + colOff + col) =
                make_float2(v2, v3);
            if (houtH) {
                half2 h = __floats2half2_rn(v2, v3);
                *(unsigned*)(houtH + (size_t)node1 * D + col) = *(unsigned*)&h;
            }
        }
    }
}

// ---------------- launch ----------------
extern "C" void kernel_launch(void* const* d_in, const int* in_sizes, int n_in,
                              void* d_out, int out_size) {
    const float* x   = (const float*)d_in[0];
    const float* W1a = (const float*)d_in[1];
    const float* W2a = (const float*)d_in[2];
    const float* W1b = (const float*)d_in[3];
    const float* W2b = (const float*)d_in[4];
    const int*   src = (const int*)d_in[5];
    const int*   dst = (const int*)d_in[6];
    float* out = (float*)d_out;

    __half* xh;  cudaGetSymbolAddress((void**)&xh,  g_xh);
    __half* hAh; cudaGetSymbolAddress((void**)&hAh, g_hAh);
    __half* hBh; cudaGetSymbolAddress((void**)&hBh, g_hBh);
    __half* wh;  cudaGetSymbolAddress((void**)&wh,  g_w16);
    void* degP;  cudaGetSymbolAddress(&degP, g_deg);
    void* tkP;   cudaGetSymbolAddress(&tkP, g_ticket);
    void* stP;   cudaGetSymbolAddress(&stP, g_state);

    cudaFuncSetAttribute(k_fused, cudaFuncAttributeMaxDynamicSharedMemorySize,
                         SMEM_BYTES);

    const int TB = 256;
    int gE = (N_EDGES + TB - 1) / TB;
    int gF = (N_NODES + NPB - 1) / NPB;   // 1563

    cudaMemsetAsync(degP, 0, N_NODES * sizeof(int));
    cudaMemsetAsync(tkP, 0, sizeof(int));
    cudaMemsetAsync(stP, 0, NTILES * sizeof(unsigned long long));

    k_count<<<gE, TB>>>(dst);
    k_scan<<<NTILES, 256>>>();
    k_fill_tohalf<<<gE, TB>>>(src, dst, x, W1a, W2a, W1b, W2b);

    k_fused<<<gF, TPB, SMEM_BYTES>>>(xh, wh,        out, hAh, 1, 0);
    k_fused<<<gF, TPB, SMEM_BYTES>>>(hAh, wh + 8192, out, hBh, 1, 64);
    k_fused<<<gF, TPB, SMEM_BYTES>>>(hBh, wh + 8192, out, (__half*)0, 0, 128);
}